// round 9
// baseline (speedup 1.0000x reference)
#include <cuda_runtime.h>
#include <cstdint>

// OptimizedUniformSampler R9: bucket-table membership + group-of-4 vector I/O.
// - 2^21 direct-index buckets over (e0, r>>6): avg 0.48 entries, 62% empty.
// - each thread processes 4 consecutive elements: 1 pos load set, LDG.128
//   rand loads, STG.128 neg/keep stores, 4 searches with batched probes.
// Output float32: neg [3T] then keep [T]. Generic bisect fallback retained.

#define THREADS 256
#define EPT 8                    // elements per thread (multiple of 4)
#define NB_BITS 21
#define NB (1 << NB_BITS)
#define EMPTY 0xFFFFFFFFu

__device__ int g_width;
__device__ int g_ok;
__device__ unsigned int g_bucket_lo[NB];   // 8 MB scratch

static __device__ __forceinline__ unsigned int bucket_of(long long h) {
    return ((unsigned int)(((unsigned long long)h >> 42) << 4)
          | (unsigned int)(((unsigned long long)h >> 27) & 15ULL)) & (NB - 1);
}

__global__ void detect_kernel(const unsigned int* __restrict__ pw, int n_words) {
    if (threadIdx.x == 0) {
        int w = 8;
        int lim = n_words < 64 ? n_words : 64;
        for (int k = 1; k < lim; k += 2)
            if (pw[k] != 0u) { w = 4; break; }
        g_width = w;
    }
}

__global__ void init_kernel() {
    int i = blockIdx.x * blockDim.x + threadIdx.x;
    if (i == 0) g_ok = 1;
    for (; i < NB / 4; i += gridDim.x * blockDim.x)
        ((uint4*)g_bucket_lo)[i] = make_uint4(EMPTY, EMPTY, EMPTY, EMPTY);
}

__global__ void build_kernel(const long long* __restrict__ hs, int L) {
    if (g_width != 8) return;
    int i = blockIdx.x * blockDim.x + threadIdx.x;
    for (; i < L; i += gridDim.x * blockDim.x) {
        long long h = __ldg(&hs[i]);
        // validity: h fits 59 bits (e0 < 2^17), bits 31..41 zero (r < 2^10)
        if (((unsigned long long)h >> 59) != 0ULL ||
            (((unsigned long long)h >> 31) & 0x7FFULL) != 0ULL)
            g_ok = 0;
        unsigned int b = bucket_of(h);
        bool first = (i == 0) || (bucket_of(__ldg(&hs[i - 1])) != b);
        if (first) g_bucket_lo[b] = (unsigned int)i;
    }
}

__global__ __launch_bounds__(THREADS)
void sampler_kernel(const void* __restrict__ posv,
                    const void* __restrict__ randv,
                    const void* __restrict__ hashv,
                    float* __restrict__ out,
                    int total, int negs_shift, int negs, int L,
                    long long keep_budget)
{
    const int W = g_width;
    const int OK = g_ok;
    const long long T = total;
    const int split = (total + 1) >> 1;
    const int base = blockIdx.x * (THREADS * EPT);
    const bool full = (base + THREADS * EPT) <= total;

    if (W == 8 && OK && full && negs_shift >= 2 && keep_budget == T && (T & 3) == 0) {
        // ================= FAST PATH =================
        const long long* pos = (const long long*)posv;
        const long long* rnd = (const long long*)randv;
        const long long* hs  = (const long long*)hashv;

        #pragma unroll
        for (int jg = 0; jg < EPT / 4; jg++) {
            const int g = jg * THREADS + threadIdx.x;
            const int i = base + 4 * g;                 // 4 consecutive elements
            const int b = i >> negs_shift;              // same row for all 4

            const long long e0 = __ldg(&pos[(long long)b * 3 + 0]);
            const long long r1 = __ldg(&pos[(long long)b * 3 + 1]);
            const long long e2 = __ldg(&pos[(long long)b * 3 + 2]);

            const ulonglong2 ra = __ldg((const ulonglong2*)&rnd[i]);
            const ulonglong2 rb = __ldg((const ulonglong2*)&rnd[i + 2]);
            long long rv[4] = { (long long)ra.x, (long long)ra.y,
                                (long long)rb.x, (long long)rb.y };

            long long h[4]; float fx[4], fy[4], fz[4];
            unsigned int bk[4];
            #pragma unroll
            for (int k = 0; k < 4; k++) {
                const bool ch = (i + k) < split;
                const long long orig = ch ? e0 : e2;
                const long long repl = rv[k] + (((rv[k] >= orig) && (orig > 0)) ? 1LL : 0LL);
                const long long a0 = ch ? repl : e0;
                const long long a2 = ch ? e2 : repl;
                h[k]  = (a0 << 42) | (r1 << 21) | a2;
                bk[k] = bucket_of(h[k]);
                fx[k] = (float)a0; fy[k] = (float)r1; fz[k] = (float)a2;
            }

            const unsigned int s0 = __ldg(&g_bucket_lo[bk[0]]);
            const unsigned int s1 = __ldg(&g_bucket_lo[bk[1]]);
            const unsigned int s2 = __ldg(&g_bucket_lo[bk[2]]);
            const unsigned int s3 = __ldg(&g_bucket_lo[bk[3]]);

            int ix[4] = { s0 == EMPTY ? L : (int)s0, s1 == EMPTY ? L : (int)s1,
                          s2 == EMPTY ? L : (int)s2, s3 == EMPTY ? L : (int)s3 };
            bool in[4] = { false, false, false, false };

            // two batched probe rounds (MLP=4 each), then rare serial cleanup
            #pragma unroll
            for (int p = 0; p < 2; p++) {
                long long v[4];
                #pragma unroll
                for (int k = 0; k < 4; k++)
                    v[k] = (ix[k] < L) ? __ldg(&hs[ix[k]]) : 0x7fffffffffffffffLL;
                #pragma unroll
                for (int k = 0; k < 4; k++) {
                    if (ix[k] < L) {
                        if (v[k] >= h[k]) { in[k] = (v[k] == h[k]); ix[k] = L; }
                        else ix[k]++;
                    }
                }
            }
            #pragma unroll
            for (int k = 0; k < 4; k++) {
                while (ix[k] < L) {
                    long long v = __ldg(&hs[ix[k]]);
                    if (v >= h[k]) { in[k] = (v == h[k]); break; }
                    ix[k]++;
                }
            }

            // 12 neg floats as 3x STG.128 (aligned: i % 4 == 0)
            float4* np = (float4*)(out + (long long)i * 3);
            __stcs(np + 0, make_float4(fx[0], fy[0], fz[0], fx[1]));
            __stcs(np + 1, make_float4(fy[1], fz[1], fx[2], fy[2]));
            __stcs(np + 2, make_float4(fz[2], fx[3], fy[3], fz[3]));
            // keep as 1x STG.128 (aligned: (3T + i) % 4 == 0)
            __stcs((float4*)(out + 3 * T + i),
                   make_float4(in[0] ? 0.0f : 1.0f, in[1] ? 0.0f : 1.0f,
                               in[2] ? 0.0f : 1.0f, in[3] ? 0.0f : 1.0f));
        }
    } else {
        // ================= GENERIC FALLBACK: plain bisect =================
        for (int j = 0; j < EPT; j++) {
            int i = base + j * THREADS + threadIdx.x;
            if (i >= total) break;
            int b = i / negs;

            long long e0, r1, e2, rv;
            if (W == 8) {
                const long long* pos = (const long long*)posv;
                e0 = __ldg(&pos[(long long)b * 3 + 0]);
                r1 = __ldg(&pos[(long long)b * 3 + 1]);
                e2 = __ldg(&pos[(long long)b * 3 + 2]);
                rv = __ldg(&((const long long*)randv)[i]);
            } else {
                const int* pos = (const int*)posv;
                e0 = __ldg(&pos[b * 3 + 0]);
                r1 = __ldg(&pos[b * 3 + 1]);
                e2 = __ldg(&pos[b * 3 + 2]);
                rv = __ldg(&((const int*)randv)[i]);
            }
            bool chd = (i < split);
            long long orig = chd ? e0 : e2;
            long long repl = rv + (((rv >= orig) && (orig > 0)) ? 1LL : 0LL);
            if (chd) e0 = repl; else e2 = repl;

            long long h;
            if (W == 8) h = (e0 << 42) | (r1 << 21) | e2;
            else        h = (long long)(int)(((int)r1 << 21) | (int)e2);

            int lo = 0, hi = L;
            if (W == 8) {
                const long long* hsg = (const long long*)hashv;
                while (lo < hi) { int m = (lo + hi) >> 1;
                                  if (__ldg(&hsg[m]) < h) lo = m + 1; else hi = m; }
            } else {
                const int* hsg = (const int*)hashv;
                int h32 = (int)h;
                while (lo < hi) { int m = (lo + hi) >> 1;
                                  if (__ldg(&hsg[m]) < h32) lo = m + 1; else hi = m; }
            }
            bool in_set;
            if (W == 8) in_set = (lo < L) && (__ldg(&((const long long*)hashv)[lo]) == h);
            else        in_set = (lo < L) && (__ldg(&((const int*)hashv)[lo]) == (int)h);

            long long o = (long long)i * 3;
            out[o + 0] = (float)e0;
            out[o + 1] = (float)r1;
            out[o + 2] = (float)e2;
            if ((long long)i < keep_budget)
                out[3 * T + i] = in_set ? 0.0f : 1.0f;
        }
    }
}

extern "C" void kernel_launch(void* const* d_in, const int* in_sizes, int n_in,
                              void* d_out, int out_size) {
    int idx[3]; int cnt = 0;
    for (int k = 0; k < n_in && cnt < 3; k++)
        if (in_sizes[k] > 1) idx[cnt++] = k;
    for (int a = 0; a < cnt; a++)
        for (int c = a + 1; c < cnt; c++)
            if (in_sizes[idx[c]] < in_sizes[idx[a]]) { int t = idx[a]; idx[a] = idx[c]; idx[c] = t; }

    int i_pos = idx[0], i_hash = idx[1], i_rand = idx[2];
    const void* pos    = d_in[i_pos];
    const void* hashes = d_in[i_hash];
    const void* rv     = d_in[i_rand];

    int total = in_sizes[i_rand];
    int B     = in_sizes[i_pos] / 3;
    int L     = in_sizes[i_hash];
    int negs  = (B > 0) ? total / B : 1;
    if (negs < 1) negs = 1;

    int negs_shift = -1;
    if ((negs & (negs - 1)) == 0) {
        negs_shift = 0;
        while ((1 << negs_shift) < negs) negs_shift++;
    }

    long long T = total;
    long long oe = out_size;
    long long keep_budget = (oe >= 3 * T) ? (oe - 3 * T) : 0;
    if (keep_budget > T) keep_budget = T;

    detect_kernel<<<1, 32>>>((const unsigned int*)pos, in_sizes[i_pos]);
    init_kernel<<<1024, THREADS>>>();
    build_kernel<<<2048, THREADS>>>((const long long*)hashes, L);

    int per_block = THREADS * EPT;
    int grid = (total + per_block - 1) / per_block;
    sampler_kernel<<<grid, THREADS>>>(pos, rv, hashes, (float*)d_out,
                                      total, negs_shift, negs, L, keep_budget);
}

// round 10
// speedup vs baseline: 1.2999x; 1.2999x over previous
#include <cuda_runtime.h>
#include <cstdint>

// OptimizedUniformSampler R10: revert to R8 register shape (32 regs, occ 80%),
// keep only zero-reg-cost R9 gains: 2^21 sparse bucket table (avg 0.48
// entries/bucket -> ~0.6 probes/elem) + streaming output stores.
// Output float32: neg [3T] then keep [T]. Generic bisect fallback retained.

#define THREADS 256
#define EPT 8
#define NB_BITS 21
#define NB (1 << NB_BITS)
#define EMPTY 0xFFFFFFFFu

__device__ int g_width;
__device__ int g_ok;
__device__ unsigned int g_bucket_lo[NB];   // 8 MB scratch

static __device__ __forceinline__ unsigned int bucket_of(long long h) {
    return ((unsigned int)(((unsigned long long)h >> 42) << 4)
          | (unsigned int)(((unsigned long long)h >> 27) & 15ULL)) & (NB - 1);
}

__global__ void detect_kernel(const unsigned int* __restrict__ pw, int n_words) {
    if (threadIdx.x == 0) {
        int w = 8;
        int lim = n_words < 64 ? n_words : 64;
        for (int k = 1; k < lim; k += 2)
            if (pw[k] != 0u) { w = 4; break; }
        g_width = w;
    }
}

__global__ void init_kernel() {
    int i = blockIdx.x * blockDim.x + threadIdx.x;
    if (i == 0) g_ok = 1;
    for (; i < NB / 4; i += gridDim.x * blockDim.x)
        ((uint4*)g_bucket_lo)[i] = make_uint4(EMPTY, EMPTY, EMPTY, EMPTY);
}

__global__ void build_kernel(const long long* __restrict__ hs, int L) {
    if (g_width != 8) return;
    int i = blockIdx.x * blockDim.x + threadIdx.x;
    for (; i < L; i += gridDim.x * blockDim.x) {
        long long h = __ldg(&hs[i]);
        // validity: h fits 59 bits (e0 < 2^17), bits 31..41 zero (r < 2^10)
        if (((unsigned long long)h >> 59) != 0ULL ||
            (((unsigned long long)h >> 31) & 0x7FFULL) != 0ULL)
            g_ok = 0;
        unsigned int b = bucket_of(h);
        bool first = (i == 0) || (bucket_of(__ldg(&hs[i - 1])) != b);
        if (first) g_bucket_lo[b] = (unsigned int)i;
    }
}

__global__ __launch_bounds__(THREADS)
void sampler_kernel(const void* __restrict__ posv,
                    const void* __restrict__ randv,
                    const void* __restrict__ hashv,
                    float* __restrict__ out,
                    int total, int negs_shift, int negs, int L,
                    long long keep_budget)
{
    const int W = g_width;
    const int OK = g_ok;
    const long long T = total;
    const int split = (total + 1) >> 1;
    const int base = blockIdx.x * (THREADS * EPT);
    const bool full = (base + THREADS * EPT) <= total;

    if (W == 8 && OK && full && negs_shift >= 0) {
        // ================= FAST PATH: bucket membership, 2-way =================
        const long long* pos = (const long long*)posv;
        const long long* rnd = (const long long*)randv;
        const long long* hs  = (const long long*)hashv;

        #pragma unroll
        for (int j = 0; j < EPT; j += 2) {
            const int i0 = base + j * THREADS + threadIdx.x;
            const int i1 = i0 + THREADS;

            const int b0 = i0 >> negs_shift;
            const int b1 = i1 >> negs_shift;
            long long e00 = __ldg(&pos[(long long)b0 * 3 + 0]);
            long long r10 = __ldg(&pos[(long long)b0 * 3 + 1]);
            long long e20 = __ldg(&pos[(long long)b0 * 3 + 2]);
            long long e01 = __ldg(&pos[(long long)b1 * 3 + 0]);
            long long r11 = __ldg(&pos[(long long)b1 * 3 + 1]);
            long long e21 = __ldg(&pos[(long long)b1 * 3 + 2]);
            long long rv0 = __ldg(&rnd[i0]);
            long long rv1 = __ldg(&rnd[i1]);

            bool ch0 = (i0 < split), ch1 = (i1 < split);
            long long or0 = ch0 ? e00 : e20;
            long long or1 = ch1 ? e01 : e21;
            long long rp0 = rv0 + (((rv0 >= or0) && (or0 > 0)) ? 1LL : 0LL);
            long long rp1 = rv1 + (((rv1 >= or1) && (or1 > 0)) ? 1LL : 0LL);
            if (ch0) e00 = rp0; else e20 = rp0;
            if (ch1) e01 = rp1; else e21 = rp1;

            const long long h0 = (e00 << 42) | (r10 << 21) | e20;
            const long long h1 = (e01 << 42) | (r11 << 21) | e21;

            const unsigned int s0 = __ldg(&g_bucket_lo[bucket_of(h0)]);
            const unsigned int s1 = __ldg(&g_bucket_lo[bucket_of(h1)]);

            bool in0 = false;
            if (s0 != EMPTY) {
                int idx = (int)s0;
                while (idx < L) {
                    long long v = __ldg(&hs[idx]);
                    if (v >= h0) { in0 = (v == h0); break; }
                    idx++;
                }
            }
            bool in1 = false;
            if (s1 != EMPTY) {
                int idx = (int)s1;
                while (idx < L) {
                    long long v = __ldg(&hs[idx]);
                    if (v >= h1) { in1 = (v == h1); break; }
                    idx++;
                }
            }

            long long o0 = (long long)i0 * 3;
            long long o1 = (long long)i1 * 3;
            __stcs(&out[o0 + 0], (float)e00);
            __stcs(&out[o0 + 1], (float)r10);
            __stcs(&out[o0 + 2], (float)e20);
            __stcs(&out[o1 + 0], (float)e01);
            __stcs(&out[o1 + 1], (float)r11);
            __stcs(&out[o1 + 2], (float)e21);
            if ((long long)i0 < keep_budget) __stcs(&out[3 * T + i0], in0 ? 0.0f : 1.0f);
            if ((long long)i1 < keep_budget) __stcs(&out[3 * T + i1], in1 ? 0.0f : 1.0f);
        }
    } else {
        // ================= GENERIC FALLBACK: plain bisect =================
        for (int j = 0; j < EPT; j++) {
            int i = base + j * THREADS + threadIdx.x;
            if (i >= total) break;
            int b = i / negs;

            long long e0, r1, e2, rv;
            if (W == 8) {
                const long long* pos = (const long long*)posv;
                e0 = __ldg(&pos[(long long)b * 3 + 0]);
                r1 = __ldg(&pos[(long long)b * 3 + 1]);
                e2 = __ldg(&pos[(long long)b * 3 + 2]);
                rv = __ldg(&((const long long*)randv)[i]);
            } else {
                const int* pos = (const int*)posv;
                e0 = __ldg(&pos[b * 3 + 0]);
                r1 = __ldg(&pos[b * 3 + 1]);
                e2 = __ldg(&pos[b * 3 + 2]);
                rv = __ldg(&((const int*)randv)[i]);
            }
            bool chd = (i < split);
            long long orig = chd ? e0 : e2;
            long long repl = rv + (((rv >= orig) && (orig > 0)) ? 1LL : 0LL);
            if (chd) e0 = repl; else e2 = repl;

            long long h;
            if (W == 8) h = (e0 << 42) | (r1 << 21) | e2;
            else        h = (long long)(int)(((int)r1 << 21) | (int)e2);

            int lo = 0, hi = L;
            if (W == 8) {
                const long long* hsg = (const long long*)hashv;
                while (lo < hi) { int m = (lo + hi) >> 1;
                                  if (__ldg(&hsg[m]) < h) lo = m + 1; else hi = m; }
            } else {
                const int* hsg = (const int*)hashv;
                int h32 = (int)h;
                while (lo < hi) { int m = (lo + hi) >> 1;
                                  if (__ldg(&hsg[m]) < h32) lo = m + 1; else hi = m; }
            }
            bool in_set;
            if (W == 8) in_set = (lo < L) && (__ldg(&((const long long*)hashv)[lo]) == h);
            else        in_set = (lo < L) && (__ldg(&((const int*)hashv)[lo]) == (int)h);

            long long o = (long long)i * 3;
            out[o + 0] = (float)e0;
            out[o + 1] = (float)r1;
            out[o + 2] = (float)e2;
            if ((long long)i < keep_budget)
                out[3 * T + i] = in_set ? 0.0f : 1.0f;
        }
    }
}

extern "C" void kernel_launch(void* const* d_in, const int* in_sizes, int n_in,
                              void* d_out, int out_size) {
    int idx[3]; int cnt = 0;
    for (int k = 0; k < n_in && cnt < 3; k++)
        if (in_sizes[k] > 1) idx[cnt++] = k;
    for (int a = 0; a < cnt; a++)
        for (int c = a + 1; c < cnt; c++)
            if (in_sizes[idx[c]] < in_sizes[idx[a]]) { int t = idx[a]; idx[a] = idx[c]; idx[c] = t; }

    int i_pos = idx[0], i_hash = idx[1], i_rand = idx[2];
    const void* pos    = d_in[i_pos];
    const void* hashes = d_in[i_hash];
    const void* rv     = d_in[i_rand];

    int total = in_sizes[i_rand];
    int B     = in_sizes[i_pos] / 3;
    int L     = in_sizes[i_hash];
    int negs  = (B > 0) ? total / B : 1;
    if (negs < 1) negs = 1;

    int negs_shift = -1;
    if ((negs & (negs - 1)) == 0) {
        negs_shift = 0;
        while ((1 << negs_shift) < negs) negs_shift++;
    }

    long long T = total;
    long long oe = out_size;
    long long keep_budget = (oe >= 3 * T) ? (oe - 3 * T) : 0;
    if (keep_budget > T) keep_budget = T;

    detect_kernel<<<1, 32>>>((const unsigned int*)pos, in_sizes[i_pos]);
    init_kernel<<<1024, THREADS>>>();
    build_kernel<<<2048, THREADS>>>((const long long*)hashes, L);

    int per_block = THREADS * EPT;
    int grid = (total + per_block - 1) / per_block;
    sampler_kernel<<<grid, THREADS>>>(pos, rv, hashes, (float*)d_out,
                                      total, negs_shift, negs, L, keep_budget);
}

// round 11
// speedup vs baseline: 1.3339x; 1.0261x over previous
#include <cuda_runtime.h>
#include <cstdint>

// OptimizedUniformSampler R11: R8 shape + consecutive-pair processing.
// Pairs (i, i+1) share the pos row (warp-uniform load), rand via LDG.128,
// neg/keep stores via STG.64. Bucket table back to 2^19 (probes proven
// non-binding in R8 vs R10). Output float32: neg [3T] then keep [T].

#define THREADS 256
#define EPT 8                    // elements per thread (even)
#define NB_BITS 19
#define NB (1 << NB_BITS)
#define EMPTY 0xFFFFFFFFu

__device__ int g_width;
__device__ int g_ok;
__device__ unsigned int g_bucket_lo[NB];   // 2 MB scratch

static __device__ __forceinline__ unsigned int bucket_of(long long h) {
    return ((unsigned int)(((unsigned long long)h >> 42) << 2)
          | (unsigned int)(((unsigned long long)h >> 29) & 3ULL)) & (NB - 1);
}

__global__ void init_kernel(const unsigned int* __restrict__ pw, int n_words) {
    int i = blockIdx.x * blockDim.x + threadIdx.x;
    if (i == 0) {
        g_ok = 1;
        int w = 8;
        int lim = n_words < 64 ? n_words : 64;
        for (int k = 1; k < lim; k += 2)
            if (pw[k] != 0u) { w = 4; break; }
        g_width = w;
    }
    for (; i < NB / 4; i += gridDim.x * blockDim.x)
        ((uint4*)g_bucket_lo)[i] = make_uint4(EMPTY, EMPTY, EMPTY, EMPTY);
}

__global__ void build_kernel(const long long* __restrict__ hs, int L) {
    if (g_width != 8) return;
    int i = blockIdx.x * blockDim.x + threadIdx.x;
    for (; i < L; i += gridDim.x * blockDim.x) {
        long long h = __ldg(&hs[i]);
        // validity: h fits 59 bits (e0 < 2^17), bits 31..41 zero (r < 2^10)
        if (((unsigned long long)h >> 59) != 0ULL ||
            (((unsigned long long)h >> 31) & 0x7FFULL) != 0ULL)
            g_ok = 0;
        unsigned int b = bucket_of(h);
        bool first = (i == 0) || (bucket_of(__ldg(&hs[i - 1])) != b);
        if (first) g_bucket_lo[b] = (unsigned int)i;
    }
}

__global__ __launch_bounds__(THREADS)
void sampler_kernel(const void* __restrict__ posv,
                    const void* __restrict__ randv,
                    const void* __restrict__ hashv,
                    float* __restrict__ out,
                    int total, int negs_shift, int negs, int L,
                    long long keep_budget)
{
    const int W = g_width;
    const int OK = g_ok;
    const long long T = total;
    const int split = (total + 1) >> 1;
    const int base = blockIdx.x * (THREADS * EPT);
    const bool full = (base + THREADS * EPT) <= total;

    if (W == 8 && OK && full && negs_shift >= 1 && keep_budget == T && (T & 1) == 0) {
        // ============ FAST PATH: consecutive pairs ============
        const long long* pos = (const long long*)posv;
        const long long* rnd = (const long long*)randv;
        const long long* hs  = (const long long*)hashv;

        #pragma unroll
        for (int jg = 0; jg < EPT / 2; jg++) {
            const int q = jg * THREADS + threadIdx.x;
            const int i = base + 2 * q;              // even; pair (i, i+1)
            const int b = i >> negs_shift;           // same row for both

            const long long e0 = __ldg(&pos[(long long)b * 3 + 0]);
            const long long r1 = __ldg(&pos[(long long)b * 3 + 1]);
            const long long e2 = __ldg(&pos[(long long)b * 3 + 2]);

            const ulonglong2 rr = __ldg((const ulonglong2*)&rnd[i]);
            const long long rv0 = (long long)rr.x;
            const long long rv1 = (long long)rr.y;

            const bool ch0 = (i < split);
            const bool ch1 = (i + 1 < split);
            const long long or0 = ch0 ? e0 : e2;
            const long long or1 = ch1 ? e0 : e2;
            const long long rp0 = rv0 + (((rv0 >= or0) && (or0 > 0)) ? 1LL : 0LL);
            const long long rp1 = rv1 + (((rv1 >= or1) && (or1 > 0)) ? 1LL : 0LL);
            const long long a00 = ch0 ? rp0 : e0;
            const long long a20 = ch0 ? e2 : rp0;
            const long long a01 = ch1 ? rp1 : e0;
            const long long a21 = ch1 ? e2 : rp1;

            const long long h0 = (a00 << 42) | (r1 << 21) | a20;
            const long long h1 = (a01 << 42) | (r1 << 21) | a21;

            const unsigned int s0 = __ldg(&g_bucket_lo[bucket_of(h0)]);
            const unsigned int s1 = __ldg(&g_bucket_lo[bucket_of(h1)]);

            bool in0 = false;
            if (s0 != EMPTY) {
                int idx = (int)s0;
                while (idx < L) {
                    long long v = __ldg(&hs[idx]);
                    if (v >= h0) { in0 = (v == h0); break; }
                    idx++;
                }
            }
            bool in1 = false;
            if (s1 != EMPTY) {
                int idx = (int)s1;
                while (idx < L) {
                    long long v = __ldg(&hs[idx]);
                    if (v >= h1) { in1 = (v == h1); break; }
                    idx++;
                }
            }

            // 6 neg floats as 3x STG.64 (3*i even)
            float2* np = (float2*)(out + (long long)i * 3);
            np[0] = make_float2((float)a00, (float)r1);
            np[1] = make_float2((float)a20, (float)a01);
            np[2] = make_float2((float)r1,  (float)a21);
            // keep pair as STG.64 (3T+i even)
            *(float2*)(out + 3 * T + i) =
                make_float2(in0 ? 0.0f : 1.0f, in1 ? 0.0f : 1.0f);
        }
    } else {
        // ============ GENERIC FALLBACK: plain bisect ============
        for (int j = 0; j < EPT; j++) {
            int i = base + j * THREADS + threadIdx.x;
            if (i >= total) break;
            int b = i / negs;

            long long e0, r1, e2, rv;
            if (W == 8) {
                const long long* pos = (const long long*)posv;
                e0 = __ldg(&pos[(long long)b * 3 + 0]);
                r1 = __ldg(&pos[(long long)b * 3 + 1]);
                e2 = __ldg(&pos[(long long)b * 3 + 2]);
                rv = __ldg(&((const long long*)randv)[i]);
            } else {
                const int* pos = (const int*)posv;
                e0 = __ldg(&pos[b * 3 + 0]);
                r1 = __ldg(&pos[b * 3 + 1]);
                e2 = __ldg(&pos[b * 3 + 2]);
                rv = __ldg(&((const int*)randv)[i]);
            }
            bool chd = (i < split);
            long long orig = chd ? e0 : e2;
            long long repl = rv + (((rv >= orig) && (orig > 0)) ? 1LL : 0LL);
            if (chd) e0 = repl; else e2 = repl;

            long long h;
            if (W == 8) h = (e0 << 42) | (r1 << 21) | e2;
            else        h = (long long)(int)(((int)r1 << 21) | (int)e2);

            int lo = 0, hi = L;
            if (W == 8) {
                const long long* hsg = (const long long*)hashv;
                while (lo < hi) { int m = (lo + hi) >> 1;
                                  if (__ldg(&hsg[m]) < h) lo = m + 1; else hi = m; }
            } else {
                const int* hsg = (const int*)hashv;
                int h32 = (int)h;
                while (lo < hi) { int m = (lo + hi) >> 1;
                                  if (__ldg(&hsg[m]) < h32) lo = m + 1; else hi = m; }
            }
            bool in_set;
            if (W == 8) in_set = (lo < L) && (__ldg(&((const long long*)hashv)[lo]) == h);
            else        in_set = (lo < L) && (__ldg(&((const int*)hashv)[lo]) == (int)h);

            long long o = (long long)i * 3;
            out[o + 0] = (float)e0;
            out[o + 1] = (float)r1;
            out[o + 2] = (float)e2;
            if ((long long)i < keep_budget)
                out[3 * T + i] = in_set ? 0.0f : 1.0f;
        }
    }
}

extern "C" void kernel_launch(void* const* d_in, const int* in_sizes, int n_in,
                              void* d_out, int out_size) {
    int idx[3]; int cnt = 0;
    for (int k = 0; k < n_in && cnt < 3; k++)
        if (in_sizes[k] > 1) idx[cnt++] = k;
    for (int a = 0; a < cnt; a++)
        for (int c = a + 1; c < cnt; c++)
            if (in_sizes[idx[c]] < in_sizes[idx[a]]) { int t = idx[a]; idx[a] = idx[c]; idx[c] = t; }

    int i_pos = idx[0], i_hash = idx[1], i_rand = idx[2];
    const void* pos    = d_in[i_pos];
    const void* hashes = d_in[i_hash];
    const void* rv     = d_in[i_rand];

    int total = in_sizes[i_rand];
    int B     = in_sizes[i_pos] / 3;
    int L     = in_sizes[i_hash];
    int negs  = (B > 0) ? total / B : 1;
    if (negs < 1) negs = 1;

    int negs_shift = -1;
    if ((negs & (negs - 1)) == 0) {
        negs_shift = 0;
        while ((1 << negs_shift) < negs) negs_shift++;
    }

    long long T = total;
    long long oe = out_size;
    long long keep_budget = (oe >= 3 * T) ? (oe - 3 * T) : 0;
    if (keep_budget > T) keep_budget = T;

    init_kernel<<<512, THREADS>>>((const unsigned int*)pos, in_sizes[i_pos]);
    build_kernel<<<2048, THREADS>>>((const long long*)hashes, L);

    int per_block = THREADS * EPT;
    int grid = (total + per_block - 1) / per_block;
    sampler_kernel<<<grid, THREADS>>>(pos, rv, hashes, (float*)d_out,
                                      total, negs_shift, negs, L, keep_budget);
}

// round 14
// speedup vs baseline: 1.3794x; 1.0341x over previous
#include <cuda_runtime.h>
#include <cstdint>

// OptimizedUniformSampler R12:
// - no init kernel: stale-tolerant bucket validation (first scan probe must
//   belong to the queried bucket; sound because build rewrites every
//   non-empty bucket each launch, and bucket id is monotone in hash)
// - block-local warp-ballot width detection (no extra launch, no race)
// - 32-bit arithmetic in the hot path (ids < 2^21): low-word loads, 32-bit
//   corruption, hash assembled from two 32-bit halves.
// Output float32: neg [3T] then keep [T]. Generic bisect fallback retained.

#define THREADS 256
#define EPT 8
#define NB_BITS 19
#define NB (1 << NB_BITS)

__device__ int g_bad;                      // monotone: set once if structure invalid
__device__ unsigned int g_bucket_lo[NB];   // 2 MB scratch; NEVER cleared

static __device__ __forceinline__ unsigned int bucket_of64(long long h) {
    return ((unsigned int)(((unsigned long long)h >> 42) << 2)
          | (unsigned int)(((unsigned long long)h >> 29) & 3ULL)) & (NB - 1);
}

// per-block width detection: returns 8 (int64) or 4 (int32)
static __device__ __forceinline__ int detect_width(const void* posv, int n_elems) {
    const unsigned int* pw = (const unsigned int*)posv;
    int lid = threadIdx.x & 31;
    int lim = n_elems < 64 ? n_elems : 64;     // words; safe lower bound for both widths
    unsigned int v = 0;
    int w = 2 * lid + 1;
    if (w < lim) v = __ldg(&pw[w]);
    unsigned int any = __ballot_sync(0xFFFFFFFFu, v != 0u);
    return any ? 4 : 8;
}

__global__ void build_kernel(const long long* __restrict__ hs, int L,
                             const void* __restrict__ posv, int pos_elems) {
    if (detect_width(posv, pos_elems) != 8) return;
    int i = blockIdx.x * blockDim.x + threadIdx.x;
    for (; i < L; i += gridDim.x * blockDim.x) {
        long long h = __ldg(&hs[i]);
        // validity: h fits 59 bits (e0 < 2^17), bits 31..41 zero (r < 2^10)
        if (((unsigned long long)h >> 59) != 0ULL ||
            (((unsigned long long)h >> 31) & 0x7FFULL) != 0ULL)
            g_bad = 1;                          // monotone, deterministic
        unsigned int b = bucket_of64(h);
        bool first = (i == 0) || (bucket_of64(__ldg(&hs[i - 1])) != b);
        if (first) g_bucket_lo[b] = (unsigned int)i;
    }
}

__global__ __launch_bounds__(THREADS)
void sampler_kernel(const void* __restrict__ posv,
                    const void* __restrict__ randv,
                    const void* __restrict__ hashv,
                    float* __restrict__ out,
                    int total, int pos_elems, int negs_shift, int negs, int L,
                    long long keep_budget)
{
    const int W = detect_width(posv, pos_elems);
    const int BAD = g_bad;
    const long long T = total;
    const int split = (total + 1) >> 1;
    const int base = blockIdx.x * (THREADS * EPT);
    const bool full = (base + THREADS * EPT) <= total;

    if (W == 8 && !BAD && full && negs_shift >= 1 && keep_budget == T && (T & 1) == 0) {
        // ============ FAST PATH: consecutive pairs, 32-bit core ============
        const int* posw      = (const int*)posv;        // low words of int64
        const long long* rnd = (const long long*)randv;
        const long long* hs  = (const long long*)hashv;

        #pragma unroll
        for (int jg = 0; jg < EPT / 2; jg++) {
            const int q = jg * THREADS + threadIdx.x;
            const int i = base + 2 * q;                 // even; pair (i, i+1)
            const int b = i >> negs_shift;              // same row for both

            const int e0 = __ldg(&posw[6 * b + 0]);     // low word of pos[b][0]
            const int r1 = __ldg(&posw[6 * b + 2]);
            const int e2 = __ldg(&posw[6 * b + 4]);

            const int4 rr = __ldg((const int4*)(rnd + i));   // (lo0,hi0,lo1,hi1)
            const int rv0 = rr.x;
            const int rv1 = rr.z;

            const bool ch0 = (i < split);
            const bool ch1 = (i + 1 < split);
            const int or0 = ch0 ? e0 : e2;
            const int or1 = ch1 ? e0 : e2;
            const int rp0 = rv0 + (((rv0 >= or0) && (or0 > 0)) ? 1 : 0);
            const int rp1 = rv1 + (((rv1 >= or1) && (or1 > 0)) ? 1 : 0);
            const int a00 = ch0 ? rp0 : e0;
            const int a20 = ch0 ? e2 : rp0;
            const int a01 = ch1 ? rp1 : e0;
            const int a21 = ch1 ? e2 : rp1;

            // h = a0<<42 | r1<<21 | a2, assembled from 32-bit halves
            const unsigned int hi0 = ((unsigned int)a00 << 10) | ((unsigned int)r1 >> 11);
            const unsigned int lo0 = ((unsigned int)r1 << 21) | (unsigned int)a20;
            const unsigned int hi1 = ((unsigned int)a01 << 10) | ((unsigned int)r1 >> 11);
            const unsigned int lo1 = ((unsigned int)r1 << 21) | (unsigned int)a21;
            const long long h0 = (long long)(((unsigned long long)hi0 << 32) | lo0);
            const long long h1 = (long long)(((unsigned long long)hi1 << 32) | lo1);

            // bucket = (a0<<2) | (r1>>8 & 3)
            const unsigned int b0 = (((unsigned int)a00 << 2) | (((unsigned int)r1 >> 8) & 3u)) & (NB - 1);
            const unsigned int b1 = (((unsigned int)a01 << 2) | (((unsigned int)r1 >> 8) & 3u)) & (NB - 1);

            const unsigned int s0 = __ldg(&g_bucket_lo[b0]);
            const unsigned int s1 = __ldg(&g_bucket_lo[b1]);

            bool in0 = false;
            if (s0 < (unsigned int)L) {
                int idx = (int)s0;
                long long v = __ldg(&hs[idx]);
                if (bucket_of64(v) == b0) {                 // stale-entry rejection
                    for (;;) {
                        if (v >= h0) { in0 = (v == h0); break; }
                        if (++idx >= L) break;
                        v = __ldg(&hs[idx]);
                    }
                }
            }
            bool in1 = false;
            if (s1 < (unsigned int)L) {
                int idx = (int)s1;
                long long v = __ldg(&hs[idx]);
                if (bucket_of64(v) == b1) {
                    for (;;) {
                        if (v >= h1) { in1 = (v == h1); break; }
                        if (++idx >= L) break;
                        v = __ldg(&hs[idx]);
                    }
                }
            }

            // 6 neg floats as 3x STG.64 (3*i even)
            float2* np = (float2*)(out + (long long)i * 3);
            np[0] = make_float2((float)a00, (float)r1);
            np[1] = make_float2((float)a20, (float)a01);
            np[2] = make_float2((float)r1,  (float)a21);
            *(float2*)(out + 3 * T + i) =
                make_float2(in0 ? 0.0f : 1.0f, in1 ? 0.0f : 1.0f);
        }
    } else {
        // ============ GENERIC FALLBACK: plain bisect ============
        for (int j = 0; j < EPT; j++) {
            int i = base + j * THREADS + threadIdx.x;
            if (i >= total) break;
            int b = i / negs;

            long long e0, r1, e2, rv;
            if (W == 8) {
                const long long* pos = (const long long*)posv;
                e0 = __ldg(&pos[(long long)b * 3 + 0]);
                r1 = __ldg(&pos[(long long)b * 3 + 1]);
                e2 = __ldg(&pos[(long long)b * 3 + 2]);
                rv = __ldg(&((const long long*)randv)[i]);
            } else {
                const int* pos = (const int*)posv;
                e0 = __ldg(&pos[b * 3 + 0]);
                r1 = __ldg(&pos[b * 3 + 1]);
                e2 = __ldg(&pos[b * 3 + 2]);
                rv = __ldg(&((const int*)randv)[i]);
            }
            bool chd = (i < split);
            long long orig = chd ? e0 : e2;
            long long repl = rv + (((rv >= orig) && (orig > 0)) ? 1LL : 0LL);
            if (chd) e0 = repl; else e2 = repl;

            long long h;
            if (W == 8) h = (e0 << 42) | (r1 << 21) | e2;
            else        h = (long long)(int)(((int)r1 << 21) | (int)e2);

            int lo = 0, hi = L;
            if (W == 8) {
                const long long* hsg = (const long long*)hashv;
                while (lo < hi) { int m = (lo + hi) >> 1;
                                  if (__ldg(&hsg[m]) < h) lo = m + 1; else hi = m; }
            } else {
                const int* hsg = (const int*)hashv;
                int h32 = (int)h;
                while (lo < hi) { int m = (lo + hi) >> 1;
                                  if (__ldg(&hsg[m]) < h32) lo = m + 1; else hi = m; }
            }
            bool in_set;
            if (W == 8) in_set = (lo < L) && (__ldg(&((const long long*)hashv)[lo]) == h);
            else        in_set = (lo < L) && (__ldg(&((const int*)hashv)[lo]) == (int)h);

            long long o = (long long)i * 3;
            out[o + 0] = (float)e0;
            out[o + 1] = (float)r1;
            out[o + 2] = (float)e2;
            if ((long long)i < keep_budget)
                out[3 * T + i] = in_set ? 0.0f : 1.0f;
        }
    }
}

extern "C" void kernel_launch(void* const* d_in, const int* in_sizes, int n_in,
                              void* d_out, int out_size) {
    int idx[3]; int cnt = 0;
    for (int k = 0; k < n_in && cnt < 3; k++)
        if (in_sizes[k] > 1) idx[cnt++] = k;
    for (int a = 0; a < cnt; a++)
        for (int c = a + 1; c < cnt; c++)
            if (in_sizes[idx[c]] < in_sizes[idx[a]]) { int t = idx[a]; idx[a] = idx[c]; idx[c] = t; }

    int i_pos = idx[0], i_hash = idx[1], i_rand = idx[2];
    const void* pos    = d_in[i_pos];
    const void* hashes = d_in[i_hash];
    const void* rv     = d_in[i_rand];

    int total = in_sizes[i_rand];
    int B     = in_sizes[i_pos] / 3;
    int L     = in_sizes[i_hash];
    int negs  = (B > 0) ? total / B : 1;
    if (negs < 1) negs = 1;

    int negs_shift = -1;
    if ((negs & (negs - 1)) == 0) {
        negs_shift = 0;
        while ((1 << negs_shift) < negs) negs_shift++;
    }

    long long T = total;
    long long oe = out_size;
    long long keep_budget = (oe >= 3 * T) ? (oe - 3 * T) : 0;
    if (keep_budget > T) keep_budget = T;

    build_kernel<<<2048, THREADS>>>((const long long*)hashes, L, pos, in_sizes[i_pos]);

    int per_block = THREADS * EPT;
    int grid = (total + per_block - 1) / per_block;
    sampler_kernel<<<grid, THREADS>>>(pos, rv, hashes, (float*)d_out,
                                      total, in_sizes[i_pos], negs_shift, negs, L,
                                      keep_budget);
}

// round 15
// speedup vs baseline: 1.3863x; 1.0050x over previous
#include <cuda_runtime.h>
#include <cstdint>

// OptimizedUniformSampler R15: Bloom-bitmap membership (1 scattered load per
// query, ~1.5% false positives fall through to exact bucket scan).
// - 8 MB bitmap, zero-initialized at module load; build sets the same bits
//   every launch (idempotent atomicOr) -> no clear pass, graph-deterministic.
// - bucket_lo table (stale-tolerant, R12 scheme) used only for FP/true hits.
// - consecutive-pair fast path, 32-bit core arithmetic.
// Output float32: neg [3T] then keep [T]. Generic bisect fallback retained.

#define THREADS 256
#define EPT 8
#define NB_BITS 19
#define NB (1 << NB_BITS)
#define BLOOM_BITS 26
#define BLOOM_WORDS (1 << (BLOOM_BITS - 5))   // 2^21 words = 8 MB

__device__ int g_bad;                         // monotone validity flag
__device__ unsigned int g_bucket_lo[NB];      // 2 MB; never cleared (stale-tolerant)
__device__ unsigned int g_bloom[BLOOM_WORDS]; // 8 MB; zero-init, idempotent build

static __device__ __forceinline__ unsigned int bucket_of64(long long h) {
    return ((unsigned int)(((unsigned long long)h >> 42) << 2)
          | (unsigned int)(((unsigned long long)h >> 29) & 3ULL)) & (NB - 1);
}

static __device__ __forceinline__ unsigned int bloom_idx(long long h) {
    return (unsigned int)(((unsigned long long)h * 0x9E3779B97F4A7C15ULL)
                          >> (64 - BLOOM_BITS));
}

// per-block width detection: returns 8 (int64) or 4 (int32)
static __device__ __forceinline__ int detect_width(const void* posv, int n_elems) {
    const unsigned int* pw = (const unsigned int*)posv;
    int lid = threadIdx.x & 31;
    int lim = n_elems < 64 ? n_elems : 64;
    unsigned int v = 0;
    int w = 2 * lid + 1;
    if (w < lim) v = __ldg(&pw[w]);
    unsigned int any = __ballot_sync(0xFFFFFFFFu, v != 0u);
    return any ? 4 : 8;
}

__global__ void build_kernel(const long long* __restrict__ hs, int L,
                             const void* __restrict__ posv, int pos_elems) {
    if (detect_width(posv, pos_elems) != 8) return;
    int i = blockIdx.x * blockDim.x + threadIdx.x;
    for (; i < L; i += gridDim.x * blockDim.x) {
        long long h = __ldg(&hs[i]);
        // validity: h fits 59 bits (e0 < 2^17), bits 31..41 zero (r < 2^10)
        if (((unsigned long long)h >> 59) != 0ULL ||
            (((unsigned long long)h >> 31) & 0x7FFULL) != 0ULL)
            g_bad = 1;
        unsigned int bi = bloom_idx(h);
        atomicOr(&g_bloom[bi >> 5], 1u << (bi & 31));   // idempotent
        unsigned int b = bucket_of64(h);
        bool first = (i == 0) || (bucket_of64(__ldg(&hs[i - 1])) != b);
        if (first) g_bucket_lo[b] = (unsigned int)i;
    }
}

// exact membership via stale-tolerant bucket scan (rare path)
static __device__ __forceinline__ bool exact_member(
        const long long* __restrict__ hs, int L, long long h, unsigned int bkt) {
    unsigned int s = __ldg(&g_bucket_lo[bkt]);
    if (s >= (unsigned int)L) return false;
    int idx = (int)s;
    long long v = __ldg(&hs[idx]);
    if (bucket_of64(v) != bkt) return false;     // stale-entry rejection
    for (;;) {
        if (v >= h) return (v == h);
        if (++idx >= L) return false;
        v = __ldg(&hs[idx]);
    }
}

__global__ __launch_bounds__(THREADS)
void sampler_kernel(const void* __restrict__ posv,
                    const void* __restrict__ randv,
                    const void* __restrict__ hashv,
                    float* __restrict__ out,
                    int total, int pos_elems, int negs_shift, int negs, int L,
                    long long keep_budget)
{
    const int W = detect_width(posv, pos_elems);
    const int BAD = g_bad;
    const long long T = total;
    const int split = (total + 1) >> 1;
    const int base = blockIdx.x * (THREADS * EPT);
    const bool full = (base + THREADS * EPT) <= total;

    if (W == 8 && !BAD && full && negs_shift >= 1 && keep_budget == T && (T & 1) == 0) {
        // ============ FAST PATH: pairs + Bloom filter ============
        const int* posw      = (const int*)posv;
        const long long* rnd = (const long long*)randv;
        const long long* hs  = (const long long*)hashv;

        #pragma unroll
        for (int jg = 0; jg < EPT / 2; jg++) {
            const int q = jg * THREADS + threadIdx.x;
            const int i = base + 2 * q;                 // pair (i, i+1)
            const int b = i >> negs_shift;

            const int e0 = __ldg(&posw[6 * b + 0]);
            const int r1 = __ldg(&posw[6 * b + 2]);
            const int e2 = __ldg(&posw[6 * b + 4]);

            const int4 rr = __ldg((const int4*)(rnd + i)); // (lo0,hi0,lo1,hi1)
            const int rv0 = rr.x;
            const int rv1 = rr.z;

            const bool ch0 = (i < split);
            const bool ch1 = (i + 1 < split);
            const int or0 = ch0 ? e0 : e2;
            const int or1 = ch1 ? e0 : e2;
            const int rp0 = rv0 + (((rv0 >= or0) && (or0 > 0)) ? 1 : 0);
            const int rp1 = rv1 + (((rv1 >= or1) && (or1 > 0)) ? 1 : 0);
            const int a00 = ch0 ? rp0 : e0;
            const int a20 = ch0 ? e2 : rp0;
            const int a01 = ch1 ? rp1 : e0;
            const int a21 = ch1 ? e2 : rp1;

            const unsigned int hi0 = ((unsigned int)a00 << 10) | ((unsigned int)r1 >> 11);
            const unsigned int lo0 = ((unsigned int)r1 << 21) | (unsigned int)a20;
            const unsigned int hi1 = ((unsigned int)a01 << 10) | ((unsigned int)r1 >> 11);
            const unsigned int lo1 = ((unsigned int)r1 << 21) | (unsigned int)a21;
            const long long h0 = (long long)(((unsigned long long)hi0 << 32) | lo0);
            const long long h1 = (long long)(((unsigned long long)hi1 << 32) | lo1);

            // Bloom probe: one scattered 4B load per query
            const unsigned int bi0 = bloom_idx(h0);
            const unsigned int bi1 = bloom_idx(h1);
            const unsigned int w0 = __ldg(&g_bloom[bi0 >> 5]);
            const unsigned int w1 = __ldg(&g_bloom[bi1 >> 5]);
            const bool maybe0 = (w0 >> (bi0 & 31)) & 1u;
            const bool maybe1 = (w1 >> (bi1 & 31)) & 1u;

            bool in0 = false, in1 = false;
            if (maybe0) {
                const unsigned int bk0 = (((unsigned int)a00 << 2)
                                        | (((unsigned int)r1 >> 8) & 3u)) & (NB - 1);
                in0 = exact_member(hs, L, h0, bk0);
            }
            if (maybe1) {
                const unsigned int bk1 = (((unsigned int)a01 << 2)
                                        | (((unsigned int)r1 >> 8) & 3u)) & (NB - 1);
                in1 = exact_member(hs, L, h1, bk1);
            }

            float2* np = (float2*)(out + (long long)i * 3);
            np[0] = make_float2((float)a00, (float)r1);
            np[1] = make_float2((float)a20, (float)a01);
            np[2] = make_float2((float)r1,  (float)a21);
            *(float2*)(out + 3 * T + i) =
                make_float2(in0 ? 0.0f : 1.0f, in1 ? 0.0f : 1.0f);
        }
    } else {
        // ============ GENERIC FALLBACK: plain bisect ============
        for (int j = 0; j < EPT; j++) {
            int i = base + j * THREADS + threadIdx.x;
            if (i >= total) break;
            int b = i / negs;

            long long e0, r1, e2, rv;
            if (W == 8) {
                const long long* pos = (const long long*)posv;
                e0 = __ldg(&pos[(long long)b * 3 + 0]);
                r1 = __ldg(&pos[(long long)b * 3 + 1]);
                e2 = __ldg(&pos[(long long)b * 3 + 2]);
                rv = __ldg(&((const long long*)randv)[i]);
            } else {
                const int* pos = (const int*)posv;
                e0 = __ldg(&pos[b * 3 + 0]);
                r1 = __ldg(&pos[b * 3 + 1]);
                e2 = __ldg(&pos[b * 3 + 2]);
                rv = __ldg(&((const int*)randv)[i]);
            }
            bool chd = (i < split);
            long long orig = chd ? e0 : e2;
            long long repl = rv + (((rv >= orig) && (orig > 0)) ? 1LL : 0LL);
            if (chd) e0 = repl; else e2 = repl;

            long long h;
            if (W == 8) h = (e0 << 42) | (r1 << 21) | e2;
            else        h = (long long)(int)(((int)r1 << 21) | (int)e2);

            int lo = 0, hi = L;
            if (W == 8) {
                const long long* hsg = (const long long*)hashv;
                while (lo < hi) { int m = (lo + hi) >> 1;
                                  if (__ldg(&hsg[m]) < h) lo = m + 1; else hi = m; }
            } else {
                const int* hsg = (const int*)hashv;
                int h32 = (int)h;
                while (lo < hi) { int m = (lo + hi) >> 1;
                                  if (__ldg(&hsg[m]) < h32) lo = m + 1; else hi = m; }
            }
            bool in_set;
            if (W == 8) in_set = (lo < L) && (__ldg(&((const long long*)hashv)[lo]) == h);
            else        in_set = (lo < L) && (__ldg(&((const int*)hashv)[lo]) == (int)h);

            long long o = (long long)i * 3;
            out[o + 0] = (float)e0;
            out[o + 1] = (float)r1;
            out[o + 2] = (float)e2;
            if ((long long)i < keep_budget)
                out[3 * T + i] = in_set ? 0.0f : 1.0f;
        }
    }
}

extern "C" void kernel_launch(void* const* d_in, const int* in_sizes, int n_in,
                              void* d_out, int out_size) {
    int idx[3]; int cnt = 0;
    for (int k = 0; k < n_in && cnt < 3; k++)
        if (in_sizes[k] > 1) idx[cnt++] = k;
    for (int a = 0; a < cnt; a++)
        for (int c = a + 1; c < cnt; c++)
            if (in_sizes[idx[c]] < in_sizes[idx[a]]) { int t = idx[a]; idx[a] = idx[c]; idx[c] = t; }

    int i_pos = idx[0], i_hash = idx[1], i_rand = idx[2];
    const void* pos    = d_in[i_pos];
    const void* hashes = d_in[i_hash];
    const void* rv     = d_in[i_rand];

    int total = in_sizes[i_rand];
    int B     = in_sizes[i_pos] / 3;
    int L     = in_sizes[i_hash];
    int negs  = (B > 0) ? total / B : 1;
    if (negs < 1) negs = 1;

    int negs_shift = -1;
    if ((negs & (negs - 1)) == 0) {
        negs_shift = 0;
        while ((1 << negs_shift) < negs) negs_shift++;
    }

    long long T = total;
    long long oe = out_size;
    long long keep_budget = (oe >= 3 * T) ? (oe - 3 * T) : 0;
    if (keep_budget > T) keep_budget = T;

    build_kernel<<<2048, THREADS>>>((const long long*)hashes, L, pos, in_sizes[i_pos]);

    int per_block = THREADS * EPT;
    int grid = (total + per_block - 1) / per_block;
    sampler_kernel<<<grid, THREADS>>>(pos, rv, hashes, (float*)d_out,
                                      total, in_sizes[i_pos], negs_shift, negs, L,
                                      keep_budget);
}